// round 7
// baseline (speedup 1.0000x reference)
#include <cuda_runtime.h>
#include <cstdint>

// ---------------- problem constants ----------------
constexpr int B   = 128;
constexpr int N   = 4096;
constexpr int OUT = 64;
constexpr int F1 = 64, F2 = 128, F3 = 256;

constexpr int TILE  = 128;   // points per CTA-iteration
constexpr int TCTAS = 8;     // tile-CTAs per batch
constexpr int NT    = 512;   // threads (16 warps -> 4 per SMSP)

// strides (floats) with +4 pad -> conflict-free fragment LDS
constexpr int S1 = 68;       // h1 rows (k-dim 64)
constexpr int S3 = 132;      // h2 rows (k-dim 128)

__device__ float g_agg[B * F3];

// ---------------- smem layout (floats) ----------------
constexpr int OFF_W1  = 0;              // 128
constexpr int OFF_B1  = 128;            // 64
constexpr int OFF_B2  = 192;            // 128
constexpr int OFF_B3  = 320;            // 256
constexpr int OFF_R   = 576;            // overlay region
// phase 1 (weight staging):
constexpr int OFF_W2T = OFF_R;                   // 128*68  = 8704
constexpr int OFF_W3T = OFF_R + 128 * S1;        // 256*132 = 33792
// phase 2 (activation buffers):
constexpr int OFF_H1A = OFF_R;                   // 128*68 = 8704
constexpr int OFF_H1B = OFF_R + TILE * S1;       // 8704
constexpr int OFF_H2  = OFF_R + 2 * TILE * S1;   // 128*132 = 16896
constexpr int SMEM_FLOATS = OFF_R + 128 * S1 + 256 * S3;   // 43072
constexpr int SMEM_TOTAL  = SMEM_FLOATS * 4;               // 172288 B

__device__ __forceinline__ float tf32r(float v) {
    uint32_t r;
    asm("cvt.rna.tf32.f32 %0, %1;" : "=r"(r) : "f"(v));
    return __uint_as_float(r);
}

__device__ __forceinline__ void mma_tf32(float* d,
                                         uint32_t a0, uint32_t a1, uint32_t a2, uint32_t a3,
                                         uint32_t b0, uint32_t b1) {
    asm volatile(
        "mma.sync.aligned.m16n8k8.row.col.f32.tf32.tf32.f32 "
        "{%0,%1,%2,%3}, {%4,%5,%6,%7}, {%8,%9}, {%0,%1,%2,%3};"
        : "+f"(d[0]), "+f"(d[1]), "+f"(d[2]), "+f"(d[3])
        : "r"(a0), "r"(a1), "r"(a2), "r"(a3), "r"(b0), "r"(b1));
}

// ---------------- kernels ----------------
__global__ void init_agg_kernel() {
    int i = blockIdx.x * blockDim.x + threadIdx.x;
    if (i < B * F3) g_agg[i] = 0.0f;
}

__global__ void __launch_bounds__(NT, 1)
phi_mma_kernel(const float* __restrict__ points, const int* __restrict__ lengths,
               const float* __restrict__ w1, const float* __restrict__ b1,
               const float* __restrict__ w2, const float* __restrict__ b2,
               const float* __restrict__ w3, const float* __restrict__ b3)
{
    const int bidx = blockIdx.y;
    const int len  = lengths[bidx];
    if (blockIdx.x * TILE >= len) return;   // block-uniform early exit

    extern __shared__ float smf[];
    float* w1s = smf + OFF_W1;
    float* b1s = smf + OFF_B1;
    float* b2s = smf + OFF_B2;
    float* b3s = smf + OFF_B3;
    float* w2t = smf + OFF_W2T;
    float* w3t = smf + OFF_W3T;
    float* h1a = smf + OFF_H1A;
    float* h1b = smf + OFF_H1B;
    float* h2  = smf + OFF_H2;
    const uint32_t* h2u = reinterpret_cast<const uint32_t*>(h2);

    const int tid = threadIdx.x;

    // ---- phase 1: stage weights (transposed [n][k], tf32) + params ----
    for (int i = tid; i < F1 * F2; i += NT) {        // w2: [64k][128n]
        int k = i >> 7, n = i & 127;
        w2t[n * S1 + k] = tf32r(w2[i]);
    }
    for (int i = tid; i < F2 * F3; i += NT) {        // w3: [128k][256n]
        int k = i >> 8, n = i & 255;
        w3t[n * S3 + k] = tf32r(w3[i]);
    }
    if (tid < 128) w1s[tid] = w1[tid];
    if (tid < 64)  b1s[tid] = b1[tid];
    if (tid < 128) b2s[tid] = b2[tid];
    if (tid < 256) b3s[tid] = b3[tid];
    __syncthreads();

    const int lane = tid & 31;
    const int wid  = tid >> 5;         // 0..15
    const int g    = lane >> 2;        // row group 0..7
    const int c    = lane & 3;         // col-in-group 0..3
    const int nb2  = wid * 8;          // this warp's L2 n-slice (8 cols)
    const int nb3  = wid * 16;         // this warp's L3 n-slice (16 cols)

    // ---- persistent B fragments + biases (registers) ----
    float b2r[8][2];                   // 1 n-tile x 8 k-frags
#pragma unroll
    for (int k = 0; k < 8; k++) {
        const int br = (nb2 + g) * S1 + k * 8 + c;
        b2r[k][0] = w2t[br];
        b2r[k][1] = w2t[br + 4];
    }
    float b3r[2][16][2];               // 2 n-tiles x 16 k-frags
#pragma unroll
    for (int nt = 0; nt < 2; nt++)
#pragma unroll
        for (int k = 0; k < 16; k++) {
            const int br = (nb3 + nt * 8 + g) * S3 + k * 8 + c;
            b3r[nt][k][0] = w3t[br];
            b3r[nt][k][1] = w3t[br + 4];
        }
    float bb2[2], bb3[2][2];
    bb2[0] = b2s[nb2 + 2 * c];
    bb2[1] = b2s[nb2 + 2 * c + 1];
#pragma unroll
    for (int nt = 0; nt < 2; nt++) {
        bb3[nt][0] = b3s[nb3 + nt * 8 + 2 * c];
        bb3[nt][1] = b3s[nb3 + nt * 8 + 2 * c + 1];
    }
    __syncthreads();      // weight smem region now dead -> reuse for h buffers

    float rm[2][2];
#pragma unroll
    for (int nt = 0; nt < 2; nt++) { rm[nt][0] = 0.0f; rm[nt][1] = 0.0f; }

    // ---- L1 producer: 2 -> 64, one pass (thread = point x col-group) ----
    auto do_L1 = [&](int tt, float* __restrict__ h1buf) {
        if (tt * TILE >= len) return;
        const int p  = tid >> 2;         // 0..127
        const int cl = tid & 3;
        const int mg = tt * TILE + p;
        float x = 0.0f, y = 0.0f;
        if (mg < len) {
            float2 pp = reinterpret_cast<const float2*>(points)[(long long)bidx * N + mg];
            x = pp.x; y = pp.y;
        }
#pragma unroll
        for (int i = 0; i < 16; i++) {
            const int f = cl + 4 * i;     // conflict-free store pattern
            float v = fmaxf(fmaf(x, w1s[f], fmaf(y, w1s[64 + f], b1s[f])), 0.0f);
            h1buf[p * S1 + f] = tf32r(v);
        }
    };

    do_L1(blockIdx.x, h1a);
    __syncthreads();

    int it = 0;
    for (int t = blockIdx.x; t * TILE < len; t += TCTAS, it++) {
        float* h1cur = (it & 1) ? h1b : h1a;
        float* h1nxt = (it & 1) ? h1a : h1b;
        const uint32_t* h1u = reinterpret_cast<const uint32_t*>(h1cur);

        // ---- layer 2: all 128m x this warp's 8n; B in registers ----
#pragma unroll
        for (int mf = 0; mf < 8; mf++) {
            float acc[4] = {0.0f, 0.0f, 0.0f, 0.0f};
#pragma unroll
            for (int k = 0; k < 8; k++) {
                const int ar = (mf * 16 + g) * S1 + k * 8 + c;
                uint32_t a0 = h1u[ar];
                uint32_t a1 = h1u[ar + 8 * S1];
                uint32_t a2 = h1u[ar + 4];
                uint32_t a3 = h1u[ar + 8 * S1 + 4];
                mma_tf32(acc, a0, a1, a2, a3,
                         __float_as_uint(b2r[k][0]), __float_as_uint(b2r[k][1]));
            }
            const int r0 = mf * 16 + g, r1 = r0 + 8;
            const int col = nb2 + 2 * c;
            *reinterpret_cast<float2*>(&h2[r0 * S3 + col]) =
                make_float2(tf32r(fmaxf(acc[0] + bb2[0], 0.0f)),
                            tf32r(fmaxf(acc[1] + bb2[1], 0.0f)));
            *reinterpret_cast<float2*>(&h2[r1 * S3 + col]) =
                make_float2(tf32r(fmaxf(acc[2] + bb2[0], 0.0f)),
                            tf32r(fmaxf(acc[3] + bb2[1], 0.0f)));
        }

        // ---- L1 for next tile (overlaps with trailing L2 work) ----
        do_L1(t + TCTAS, h1nxt);
        __syncthreads();            // h2 complete; h1nxt complete

        // ---- layer 3: all 128m x this warp's 16n; B in registers ----
#pragma unroll
        for (int mf = 0; mf < 8; mf++) {
            float acc[2][4];
#pragma unroll
            for (int nt = 0; nt < 2; nt++)
#pragma unroll
                for (int j = 0; j < 4; j++) acc[nt][j] = 0.0f;

#pragma unroll
            for (int k = 0; k < 16; k++) {
                const int ar = (mf * 16 + g) * S3 + k * 8 + c;
                uint32_t a0 = h2u[ar];
                uint32_t a1 = h2u[ar + 8 * S3];
                uint32_t a2 = h2u[ar + 4];
                uint32_t a3 = h2u[ar + 8 * S3 + 4];
#pragma unroll
                for (int nt = 0; nt < 2; nt++)
                    mma_tf32(acc[nt], a0, a1, a2, a3,
                             __float_as_uint(b3r[nt][k][0]), __float_as_uint(b3r[nt][k][1]));
            }
            // epilogue: bias + relu + validity mask + running max
            const int r0 = t * TILE + mf * 16 + g;
            const int r1 = r0 + 8;
            const bool v0 = r0 < len, v1 = r1 < len;
#pragma unroll
            for (int nt = 0; nt < 2; nt++) {
                float x0 = v0 ? fmaxf(acc[nt][0] + bb3[nt][0], 0.0f) : 0.0f;
                float x1 = v0 ? fmaxf(acc[nt][1] + bb3[nt][1], 0.0f) : 0.0f;
                float y0 = v1 ? fmaxf(acc[nt][2] + bb3[nt][0], 0.0f) : 0.0f;
                float y1 = v1 ? fmaxf(acc[nt][3] + bb3[nt][1], 0.0f) : 0.0f;
                rm[nt][0] = fmaxf(rm[nt][0], fmaxf(x0, y0));
                rm[nt][1] = fmaxf(rm[nt][1], fmaxf(x1, y1));
            }
        }
        __syncthreads();            // h2 free for next L2
    }

    // ---- reduce over row-groups; cols disjoint per warp -> direct atomic ----
#pragma unroll
    for (int nt = 0; nt < 2; nt++) {
#pragma unroll
        for (int j = 0; j < 2; j++) {
            float v = rm[nt][j];
            v = fmaxf(v, __shfl_xor_sync(0xFFFFFFFFu, v, 4));
            v = fmaxf(v, __shfl_xor_sync(0xFFFFFFFFu, v, 8));
            v = fmaxf(v, __shfl_xor_sync(0xFFFFFFFFu, v, 16));
            if (g == 0)
                atomicMax(reinterpret_cast<int*>(&g_agg[bidx * F3 + nb3 + nt * 8 + 2 * c + j]),
                          __float_as_int(v));
        }
    }
}

__global__ void __launch_bounds__(256)
rho_kernel(const float* __restrict__ r1w, const float* __restrict__ r1b,
           const float* __restrict__ r2w, const float* __restrict__ r2b,
           const float* __restrict__ r3w, const float* __restrict__ r3b,
           float* __restrict__ out)
{
    __shared__ float a[256], z1[256], z2[128];
    const int b   = blockIdx.x;
    const int tid = threadIdx.x;

    a[tid] = g_agg[b * F3 + tid];
    __syncthreads();

    float acc = r1b[tid];
#pragma unroll 4
    for (int k = 0; k < 256; k++) acc = fmaf(a[k], r1w[k * 256 + tid], acc);
    z1[tid] = fmaxf(acc, 0.0f);
    __syncthreads();

    if (tid < 128) {
        float acc2 = r2b[tid];
#pragma unroll 4
        for (int k = 0; k < 256; k++) acc2 = fmaf(z1[k], r2w[k * 128 + tid], acc2);
        z2[tid] = fmaxf(acc2, 0.0f);
    }
    __syncthreads();

    if (tid < 64) {
        float acc3 = r3b[tid];
#pragma unroll 4
        for (int k = 0; k < 128; k++) acc3 = fmaf(z2[k], r3w[k * 64 + tid], acc3);
        out[b * OUT + tid] = acc3;
    }
}

// ---------------- launch ----------------
extern "C" void kernel_launch(void* const* d_in, const int* in_sizes, int n_in,
                              void* d_out, int out_size)
{
    (void)in_sizes; (void)n_in; (void)out_size;
    const float* points = (const float*)d_in[0];
    const int*   lengths= (const int*)  d_in[1];
    const float* w1  = (const float*)d_in[2];
    const float* b1  = (const float*)d_in[3];
    const float* w2  = (const float*)d_in[4];
    const float* b2  = (const float*)d_in[5];
    const float* w3  = (const float*)d_in[6];
    const float* b3  = (const float*)d_in[7];
    const float* r1w = (const float*)d_in[8];
    const float* r1b = (const float*)d_in[9];
    const float* r2w = (const float*)d_in[10];
    const float* r2b = (const float*)d_in[11];
    const float* r3w = (const float*)d_in[12];
    const float* r3b = (const float*)d_in[13];

    cudaFuncSetAttribute(phi_mma_kernel,
                         cudaFuncAttributeMaxDynamicSharedMemorySize, SMEM_TOTAL);

    init_agg_kernel<<<(B * F3 + 255) / 256, 256>>>();
    phi_mma_kernel<<<dim3(TCTAS, B), NT, SMEM_TOTAL>>>(
        points, lengths, w1, b1, w2, b2, w3, b3);
    rho_kernel<<<B, 256>>>(r1w, r1b, r2w, r2b, r3w, r3b, (float*)d_out);
}

// round 8
// speedup vs baseline: 1.7658x; 1.7658x over previous
#include <cuda_runtime.h>
#include <cuda_fp16.h>
#include <cstdint>

// ---------------- problem constants ----------------
constexpr int B   = 128;
constexpr int N   = 4096;
constexpr int OUT = 64;
constexpr int F1 = 64, F2 = 128, F3 = 256;

constexpr int TILE  = 128;   // points per CTA-iteration
constexpr int TCTAS = 8;     // tile-CTAs per batch
constexpr int NT    = 512;   // threads (16 warps)

// half strides with +8 pad -> conflict-free (word stride mod 32 == 4)
constexpr int S1H = 72;      // h1 / wt2 rows (k-dim 64)   -> 36 words
constexpr int S3H = 136;     // h2 / wt3 rows (k-dim 128)  -> 68 words
constexpr int S1W = S1H / 2;
constexpr int S3W = S3H / 2;

__device__ float g_agg[B * F3];
__device__ __align__(16) __half wt2g[F2 * S1H];   // [128 n][72 k] fp16
__device__ __align__(16) __half wt3g[F3 * S3H];   // [256 n][136 k] fp16

// ---------------- smem layout ----------------
constexpr int OFF_W1 = 0;                      // 128 floats
constexpr int OFF_B1 = 512;                    // 64 floats (bytes 512..768)
constexpr int OFF_H  = 768;                    // half buffers
constexpr int H1_BYTES = TILE * S1H * 2;       // 18432
constexpr int H2_BYTES = TILE * S3H * 2;       // 34816
constexpr int OFF_H1A = OFF_H;
constexpr int OFF_H1B = OFF_H1A + H1_BYTES;
constexpr int OFF_H2  = OFF_H1B + H1_BYTES;
constexpr int SMEM_TOTAL = OFF_H2 + H2_BYTES;  // 72448 B

__device__ __forceinline__ void mma_f16(float* d,
                                        uint32_t a0, uint32_t a1, uint32_t a2, uint32_t a3,
                                        uint32_t b0, uint32_t b1) {
    asm volatile(
        "mma.sync.aligned.m16n8k16.row.col.f32.f16.f16.f32 "
        "{%0,%1,%2,%3}, {%4,%5,%6,%7}, {%8,%9}, {%0,%1,%2,%3};"
        : "+f"(d[0]), "+f"(d[1]), "+f"(d[2]), "+f"(d[3])
        : "r"(a0), "r"(a1), "r"(a2), "r"(a3), "r"(b0), "r"(b1));
}

__device__ __forceinline__ uint32_t packh2(float lo, float hi) {
    __half2 h = __floats2half2_rn(lo, hi);
    return *reinterpret_cast<uint32_t*>(&h);
}

// ---------------- prep: zero agg + convert weights to fp16 fragments ----------------
__global__ void prep_kernel(const float* __restrict__ w2, const float* __restrict__ w3) {
    int i = blockIdx.x * 256 + threadIdx.x;
    if (i < B * F3) g_agg[i] = 0.0f;
    if (i < F1 * F2) {           // w2: [64 k][128 n] -> wt2g[n][k]
        int k = i >> 7, n = i & 127;
        wt2g[n * S1H + k] = __float2half_rn(w2[i]);
    }
    if (i < F2 * F3) {           // w3: [128 k][256 n] -> wt3g[n][k]
        int k = i >> 8, n = i & 255;
        wt3g[n * S3H + k] = __float2half_rn(w3[i]);
    }
}

// ---------------- phi ----------------
__global__ void __launch_bounds__(NT, 1)
phi_mma_kernel(const float* __restrict__ points, const int* __restrict__ lengths,
               const float* __restrict__ w1, const float* __restrict__ b1,
               const float* __restrict__ b2, const float* __restrict__ b3)
{
    const int bidx = blockIdx.y;
    const int len  = lengths[bidx];
    if (blockIdx.x * TILE >= len) return;   // block-uniform early exit

    extern __shared__ char smem[];
    float* w1s = reinterpret_cast<float*>(smem + OFF_W1);
    float* b1s = reinterpret_cast<float*>(smem + OFF_B1);
    uint32_t* h1aw = reinterpret_cast<uint32_t*>(smem + OFF_H1A);
    uint32_t* h1bw = reinterpret_cast<uint32_t*>(smem + OFF_H1B);
    uint32_t* h2w  = reinterpret_cast<uint32_t*>(smem + OFF_H2);

    const int tid  = threadIdx.x;
    const int lane = tid & 31;
    const int wid  = tid >> 5;         // 0..15
    const int g    = lane >> 2;        // row group 0..7
    const int c    = lane & 3;         // col-in-group 0..3
    const int nb2  = wid * 8;          // L2 n-slice (8 cols)
    const int nb3  = wid * 16;         // L3 n-slice (16 cols)

    if (tid < 128) w1s[tid] = w1[tid];
    else if (tid < 192) b1s[tid - 128] = b1[tid - 128];

    // ---- B fragments straight from global (L2-resident after first CTAs) ----
    const uint32_t* w2w = reinterpret_cast<const uint32_t*>(wt2g);
    const uint32_t* w3w = reinterpret_cast<const uint32_t*>(wt3g);
    uint32_t b2r[4][2];
#pragma unroll
    for (int ks = 0; ks < 4; ks++) {
        const int base = (nb2 + g) * S1W + ks * 8 + c;
        b2r[ks][0] = w2w[base];
        b2r[ks][1] = w2w[base + 4];
    }
    uint32_t b3r[2][8][2];
#pragma unroll
    for (int nt = 0; nt < 2; nt++)
#pragma unroll
        for (int ks = 0; ks < 8; ks++) {
            const int base = (nb3 + nt * 8 + g) * S3W + ks * 8 + c;
            b3r[nt][ks][0] = w3w[base];
            b3r[nt][ks][1] = w3w[base + 4];
        }
    float bb2[2], bb3[2][2];
    bb2[0] = b2[nb2 + 2 * c];
    bb2[1] = b2[nb2 + 2 * c + 1];
#pragma unroll
    for (int nt = 0; nt < 2; nt++) {
        bb3[nt][0] = b3[nb3 + nt * 8 + 2 * c];
        bb3[nt][1] = b3[nb3 + nt * 8 + 2 * c + 1];
    }

    float rm[2][2];
#pragma unroll
    for (int nt = 0; nt < 2; nt++) { rm[nt][0] = 0.0f; rm[nt][1] = 0.0f; }

    // ---- L1 producer: 2 -> 64 fp32 -> half2 pairs ----
    auto do_L1 = [&](int tt, uint32_t* __restrict__ h1w) {
        if (tt * TILE >= len) return;
        const int p  = tid >> 2;         // 0..127
        const int cl = tid & 3;
        const int mg = tt * TILE + p;
        float x = 0.0f, y = 0.0f;
        if (mg < len) {
            float2 pp = reinterpret_cast<const float2*>(points)[(long long)bidx * N + mg];
            x = pp.x; y = pp.y;
        }
#pragma unroll
        for (int i = 0; i < 8; i++) {
            const int f = 8 * i + 2 * cl;     // feature pair (f, f+1)
            float v0 = fmaxf(fmaf(x, w1s[f],     fmaf(y, w1s[64 + f],     b1s[f])),     0.0f);
            float v1 = fmaxf(fmaf(x, w1s[f + 1], fmaf(y, w1s[64 + f + 1], b1s[f + 1])), 0.0f);
            h1w[p * S1W + 4 * i + cl] = packh2(v0, v1);   // bank 4p+cl: conflict-free
        }
    };

    __syncthreads();     // w1s/b1s visible
    do_L1(blockIdx.x, h1aw);
    __syncthreads();

    int it = 0;
    for (int t = blockIdx.x; t * TILE < len; t += TCTAS, it++) {
        const uint32_t* h1w = (it & 1) ? h1bw : h1aw;
        uint32_t*       h1n = (it & 1) ? h1aw : h1bw;

        // ---- layer 2: 128m x warp's 8n, K=64 (4 fp16 MMA steps) ----
#pragma unroll
        for (int mf = 0; mf < 8; mf++) {
            float acc[4] = {0.0f, 0.0f, 0.0f, 0.0f};
#pragma unroll
            for (int ks = 0; ks < 4; ks++) {
                const int base = (mf * 16 + g) * S1W + ks * 8 + c;
                uint32_t a0 = h1w[base];
                uint32_t a1 = h1w[base + 8 * S1W];
                uint32_t a2 = h1w[base + 4];
                uint32_t a3 = h1w[base + 8 * S1W + 4];
                mma_f16(acc, a0, a1, a2, a3, b2r[ks][0], b2r[ks][1]);
            }
            const int r0 = mf * 16 + g, r1 = r0 + 8;
            const int cw = nb2 / 2 + c;
            h2w[r0 * S3W + cw] = packh2(fmaxf(acc[0] + bb2[0], 0.0f),
                                        fmaxf(acc[1] + bb2[1], 0.0f));
            h2w[r1 * S3W + cw] = packh2(fmaxf(acc[2] + bb2[0], 0.0f),
                                        fmaxf(acc[3] + bb2[1], 0.0f));
        }

        // ---- L1 for next tile overlaps trailing L2 ----
        do_L1(t + TCTAS, h1n);
        __syncthreads();            // h2 + h1next complete

        // ---- layer 3: 128m x warp's 16n, K=128 (8 fp16 MMA steps) ----
#pragma unroll
        for (int mf = 0; mf < 8; mf++) {
            float acc[2][4];
#pragma unroll
            for (int nt = 0; nt < 2; nt++)
#pragma unroll
                for (int j = 0; j < 4; j++) acc[nt][j] = 0.0f;

#pragma unroll
            for (int ks = 0; ks < 8; ks++) {
                const int base = (mf * 16 + g) * S3W + ks * 8 + c;
                uint32_t a0 = h2w[base];
                uint32_t a1 = h2w[base + 8 * S3W];
                uint32_t a2 = h2w[base + 4];
                uint32_t a3 = h2w[base + 8 * S3W + 4];
#pragma unroll
                for (int nt = 0; nt < 2; nt++)
                    mma_f16(acc[nt], a0, a1, a2, a3, b3r[nt][ks][0], b3r[nt][ks][1]);
            }
            // epilogue: bias + relu + validity mask + running max (fp32)
            const int r0 = t * TILE + mf * 16 + g;
            const int r1 = r0 + 8;
            const bool v0 = r0 < len, v1 = r1 < len;
#pragma unroll
            for (int nt = 0; nt < 2; nt++) {
                float x0 = v0 ? fmaxf(acc[nt][0] + bb3[nt][0], 0.0f) : 0.0f;
                float x1 = v0 ? fmaxf(acc[nt][1] + bb3[nt][1], 0.0f) : 0.0f;
                float y0 = v1 ? fmaxf(acc[nt][2] + bb3[nt][0], 0.0f) : 0.0f;
                float y1 = v1 ? fmaxf(acc[nt][3] + bb3[nt][1], 0.0f) : 0.0f;
                rm[nt][0] = fmaxf(rm[nt][0], fmaxf(x0, y0));
                rm[nt][1] = fmaxf(rm[nt][1], fmaxf(x1, y1));
            }
        }
        __syncthreads();            // h2 free for next L2
    }

    // ---- reduce over row-groups; cols disjoint per warp -> direct atomic ----
#pragma unroll
    for (int nt = 0; nt < 2; nt++) {
#pragma unroll
        for (int j = 0; j < 2; j++) {
            float v = rm[nt][j];
            v = fmaxf(v, __shfl_xor_sync(0xFFFFFFFFu, v, 4));
            v = fmaxf(v, __shfl_xor_sync(0xFFFFFFFFu, v, 8));
            v = fmaxf(v, __shfl_xor_sync(0xFFFFFFFFu, v, 16));
            if (g == 0)
                atomicMax(reinterpret_cast<int*>(&g_agg[bidx * F3 + nb3 + nt * 8 + 2 * c + j]),
                          __float_as_int(v));
        }
    }
}

__global__ void __launch_bounds__(256)
rho_kernel(const float* __restrict__ r1w, const float* __restrict__ r1b,
           const float* __restrict__ r2w, const float* __restrict__ r2b,
           const float* __restrict__ r3w, const float* __restrict__ r3b,
           float* __restrict__ out)
{
    __shared__ float a[256], z1[256], z2[128];
    const int b   = blockIdx.x;
    const int tid = threadIdx.x;

    a[tid] = g_agg[b * F3 + tid];
    __syncthreads();

    float acc = r1b[tid];
#pragma unroll 4
    for (int k = 0; k < 256; k++) acc = fmaf(a[k], r1w[k * 256 + tid], acc);
    z1[tid] = fmaxf(acc, 0.0f);
    __syncthreads();

    if (tid < 128) {
        float acc2 = r2b[tid];
#pragma unroll 4
        for (int k = 0; k < 256; k++) acc2 = fmaf(z1[k], r2w[k * 128 + tid], acc2);
        z2[tid] = fmaxf(acc2, 0.0f);
    }
    __syncthreads();

    if (tid < 64) {
        float acc3 = r3b[tid];
#pragma unroll 4
        for (int k = 0; k < 128; k++) acc3 = fmaf(z2[k], r3w[k * 64 + tid], acc3);
        out[b * OUT + tid] = acc3;
    }
}

// ---------------- launch ----------------
extern "C" void kernel_launch(void* const* d_in, const int* in_sizes, int n_in,
                              void* d_out, int out_size)
{
    (void)in_sizes; (void)n_in; (void)out_size;
    const float* points = (const float*)d_in[0];
    const int*   lengths= (const int*)  d_in[1];
    const float* w1  = (const float*)d_in[2];
    const float* b1  = (const float*)d_in[3];
    const float* w2  = (const float*)d_in[4];
    const float* b2  = (const float*)d_in[5];
    const float* w3  = (const float*)d_in[6];
    const float* b3  = (const float*)d_in[7];
    const float* r1w = (const float*)d_in[8];
    const float* r1b = (const float*)d_in[9];
    const float* r2w = (const float*)d_in[10];
    const float* r2b = (const float*)d_in[11];
    const float* r3w = (const float*)d_in[12];
    const float* r3b = (const float*)d_in[13];

    cudaFuncSetAttribute(phi_mma_kernel,
                         cudaFuncAttributeMaxDynamicSharedMemorySize, SMEM_TOTAL);

    prep_kernel<<<128, 256>>>(w2, w3);
    phi_mma_kernel<<<dim3(TCTAS, B), NT, SMEM_TOTAL>>>(
        points, lengths, w1, b1, b2, b3);
    rho_kernel<<<B, 256>>>(r1w, r1b, r2w, r2b, r3w, r3b, (float*)d_out);
}

// round 9
// speedup vs baseline: 1.8589x; 1.0527x over previous
#include <cuda_runtime.h>
#include <cuda_fp16.h>
#include <cstdint>

// ---------------- problem constants ----------------
constexpr int B   = 128;
constexpr int N   = 4096;
constexpr int OUT = 64;
constexpr int F1 = 64, F2 = 128, F3 = 256;

constexpr int TILE  = 128;          // points per work item
constexpr int MAXT  = N / TILE;     // 32 tiles max per batch
constexpr int MAXW  = B * MAXT;     // 4096 work items
constexpr int GRID  = 152;          // persistent CTAs (GB300 SM count)
constexpr int NT    = 512;          // threads (16 warps)

// half strides with +8 pad -> conflict-free fragment access
constexpr int S1H = 72;             // h1 / wt2 rows (k-dim 64)
constexpr int S3H = 136;            // h2 / wt3 rows (k-dim 128)
constexpr int S1W = S1H / 2;        // 36 words (row = 144 B, 16B-aligned)
constexpr int S3W = S3H / 2;        // 68 words (row = 272 B, 16B-aligned)

__device__ float g_agg[B * F3];
__device__ int   g_work;
__device__ __align__(16) __half wt2g[F2 * S1H];   // [128 n][72 k] fp16
__device__ __align__(16) __half wt3g[F3 * S3H];   // [256 n][136 k] fp16

// ---------------- smem layout (bytes) ----------------
constexpr int OFF_W1  = 0;                     // 128 floats
constexpr int OFF_B1  = 512;                   // 64 floats
constexpr int OFF_WID = 768;                   // 1 int (padded)
constexpr int OFF_H1  = 1024;                  // 128*72 halves = 18432 B
constexpr int OFF_H2  = OFF_H1 + TILE * S1H * 2;   // 19456
constexpr int SMEM_TOTAL = OFF_H2 + TILE * S3H * 2; // 54272 B

__device__ __forceinline__ void mma_f16(float* d,
                                        uint32_t a0, uint32_t a1, uint32_t a2, uint32_t a3,
                                        uint32_t b0, uint32_t b1) {
    asm volatile(
        "mma.sync.aligned.m16n8k16.row.col.f32.f16.f16.f32 "
        "{%0,%1,%2,%3}, {%4,%5,%6,%7}, {%8,%9}, {%0,%1,%2,%3};"
        : "+f"(d[0]), "+f"(d[1]), "+f"(d[2]), "+f"(d[3])
        : "r"(a0), "r"(a1), "r"(a2), "r"(a3), "r"(b0), "r"(b1));
}

__device__ __forceinline__ void ldsm4(uint32_t& r0, uint32_t& r1, uint32_t& r2, uint32_t& r3,
                                      uint32_t saddr) {
    asm volatile("ldmatrix.sync.aligned.m8n8.x4.shared.b16 {%0,%1,%2,%3}, [%4];"
                 : "=r"(r0), "=r"(r1), "=r"(r2), "=r"(r3) : "r"(saddr));
}

__device__ __forceinline__ uint32_t packh2(float lo, float hi) {
    __half2 h = __floats2half2_rn(lo, hi);
    return *reinterpret_cast<uint32_t*>(&h);
}

__device__ __forceinline__ uint32_t smem_u32(const void* p) {
    uint32_t a;
    asm("{ .reg .u64 t; cvta.to.shared.u64 t, %1; cvt.u32.u64 %0, t; }" : "=r"(a) : "l"(p));
    return a;
}

// ---------------- prep: reset counter/agg + convert weights ----------------
__global__ void prep_kernel(const float* __restrict__ w2, const float* __restrict__ w3) {
    int i = blockIdx.x * 256 + threadIdx.x;
    if (i == 0) g_work = 0;
    if (i < B * F3) g_agg[i] = 0.0f;
    if (i < F1 * F2) {           // w2: [64 k][128 n] -> wt2g[n][k]
        int k = i >> 7, n = i & 127;
        wt2g[n * S1H + k] = __float2half_rn(w2[i]);
    }
    if (i < F2 * F3) {           // w3: [128 k][256 n] -> wt3g[n][k]
        int k = i >> 8, n = i & 255;
        wt3g[n * S3H + k] = __float2half_rn(w3[i]);
    }
}

// ---------------- phi: persistent work-stealing ----------------
__global__ void __launch_bounds__(NT, 1)
phi_mma_kernel(const float* __restrict__ points, const int* __restrict__ lengths,
               const float* __restrict__ w1, const float* __restrict__ b1,
               const float* __restrict__ b2, const float* __restrict__ b3)
{
    extern __shared__ char smem[];
    float* w1s = reinterpret_cast<float*>(smem + OFF_W1);
    float* b1s = reinterpret_cast<float*>(smem + OFF_B1);
    int*   s_wid = reinterpret_cast<int*>(smem + OFF_WID);
    uint32_t* h1w = reinterpret_cast<uint32_t*>(smem + OFF_H1);
    uint32_t* h2w = reinterpret_cast<uint32_t*>(smem + OFF_H2);
    const uint32_t sb = smem_u32(smem);

    const int tid  = threadIdx.x;
    const int lane = tid & 31;
    const int wid  = tid >> 5;         // 0..15
    const int g    = lane >> 2;        // row group 0..7
    const int c    = lane & 3;         // col-in-group 0..3
    const int nb2  = wid * 8;          // L2 n-slice (8 cols)
    const int nb3  = wid * 16;         // L3 n-slice (16 cols)

    if (tid < 128) w1s[tid] = w1[tid];
    else if (tid < 192) b1s[tid - 128] = b1[tid - 128];

    // ---- persistent B fragments + biases (registers, batch-independent) ----
    const uint32_t* w2w = reinterpret_cast<const uint32_t*>(wt2g);
    const uint32_t* w3w = reinterpret_cast<const uint32_t*>(wt3g);
    uint32_t b2r[4][2];
#pragma unroll
    for (int ks = 0; ks < 4; ks++) {
        const int base = (nb2 + g) * S1W + ks * 8 + c;
        b2r[ks][0] = w2w[base];
        b2r[ks][1] = w2w[base + 4];
    }
    uint32_t b3r[2][8][2];
#pragma unroll
    for (int nt = 0; nt < 2; nt++)
#pragma unroll
        for (int ks = 0; ks < 8; ks++) {
            const int base = (nb3 + nt * 8 + g) * S3W + ks * 8 + c;
            b3r[nt][ks][0] = w3w[base];
            b3r[nt][ks][1] = w3w[base + 4];
        }
    float bb2[2], bb3[2][2];
    bb2[0] = b2[nb2 + 2 * c];
    bb2[1] = b2[nb2 + 2 * c + 1];
#pragma unroll
    for (int nt = 0; nt < 2; nt++) {
        bb3[nt][0] = b3[nb3 + nt * 8 + 2 * c];
        bb3[nt][1] = b3[nb3 + nt * 8 + 2 * c + 1];
    }

    // ---- ldmatrix per-lane base addresses ----
    // x4 tiles: t0=(rows 0-7,k0-7) t1=(rows 8-15,k0-7) t2=(rows 0-7,k8-15) t3=(rows 8-15,k8-15)
    const int tsel = lane >> 3, rr = lane & 7;
    const int lrow = (tsel & 1) * 8 + rr;
    const int lcol = (tsel >> 1) * 4;          // word offset
    const uint32_t a1base = sb + OFF_H1 + (lrow * S1W + lcol) * 4;
    const uint32_t a2base = sb + OFF_H2 + (lrow * S3W + lcol) * 4;

    __syncthreads();

    for (;;) {
        if (tid == 0) *s_wid = atomicAdd(&g_work, 1);
        __syncthreads();
        const int w = *s_wid;
        if (w >= MAXW) break;
        const int bidx   = w & (B - 1);
        const int t      = w >> 7;
        const int len    = lengths[bidx];
        const int base_m = t * TILE;
        if (base_m >= len) { __syncthreads(); continue; }

        // ---- layer 1: 2 -> 64 fp32 -> half2 ----
        {
            const int p  = tid >> 2;
            const int cl = tid & 3;
            const int mg = base_m + p;
            float x = 0.0f, y = 0.0f;
            if (mg < len) {
                float2 pp = reinterpret_cast<const float2*>(points)[(long long)bidx * N + mg];
                x = pp.x; y = pp.y;
            }
#pragma unroll
            for (int i = 0; i < 8; i++) {
                const int f = 8 * i + 2 * cl;
                float v0 = fmaxf(fmaf(x, w1s[f],     fmaf(y, w1s[64 + f],     b1s[f])),     0.0f);
                float v1 = fmaxf(fmaf(x, w1s[f + 1], fmaf(y, w1s[64 + f + 1], b1s[f + 1])), 0.0f);
                h1w[p * S1W + 4 * i + cl] = packh2(v0, v1);
            }
        }
        __syncthreads();

        // ---- layer 2: 128m x warp's 8n, K=64 ----
#pragma unroll
        for (int mf = 0; mf < 8; mf++) {
            float acc[4] = {0.0f, 0.0f, 0.0f, 0.0f};
#pragma unroll
            for (int ks = 0; ks < 4; ks++) {
                uint32_t a0, a1, a2, a3;
                ldsm4(a0, a1, a2, a3, a1base + (mf * 16 * S1W + ks * 8) * 4);
                mma_f16(acc, a0, a1, a2, a3, b2r[ks][0], b2r[ks][1]);
            }
            const int r0 = mf * 16 + g, r1 = r0 + 8;
            const int cw = nb2 / 2 + c;
            h2w[r0 * S3W + cw] = packh2(fmaxf(acc[0] + bb2[0], 0.0f),
                                        fmaxf(acc[1] + bb2[1], 0.0f));
            h2w[r1 * S3W + cw] = packh2(fmaxf(acc[2] + bb2[0], 0.0f),
                                        fmaxf(acc[3] + bb2[1], 0.0f));
        }
        __syncthreads();

        // ---- layer 3: 128m x warp's 16n, K=128; per-tile running max ----
        float rm[2][2] = {{0.0f, 0.0f}, {0.0f, 0.0f}};
#pragma unroll
        for (int mf = 0; mf < 8; mf++) {
            float acc[2][4];
#pragma unroll
            for (int nt = 0; nt < 2; nt++)
#pragma unroll
                for (int j = 0; j < 4; j++) acc[nt][j] = 0.0f;

#pragma unroll
            for (int ks = 0; ks < 8; ks++) {
                uint32_t a0, a1, a2, a3;
                ldsm4(a0, a1, a2, a3, a2base + (mf * 16 * S3W + ks * 8) * 4);
#pragma unroll
                for (int nt = 0; nt < 2; nt++)
                    mma_f16(acc[nt], a0, a1, a2, a3, b3r[nt][ks][0], b3r[nt][ks][1]);
            }
            const int r0 = base_m + mf * 16 + g;
            const int r1 = r0 + 8;
            const bool v0 = r0 < len, v1 = r1 < len;
#pragma unroll
            for (int nt = 0; nt < 2; nt++) {
                float x0 = v0 ? fmaxf(acc[nt][0] + bb3[nt][0], 0.0f) : 0.0f;
                float x1 = v0 ? fmaxf(acc[nt][1] + bb3[nt][1], 0.0f) : 0.0f;
                float y0 = v1 ? fmaxf(acc[nt][2] + bb3[nt][0], 0.0f) : 0.0f;
                float y1 = v1 ? fmaxf(acc[nt][3] + bb3[nt][1], 0.0f) : 0.0f;
                rm[nt][0] = fmaxf(rm[nt][0], fmaxf(x0, y0));
                rm[nt][1] = fmaxf(rm[nt][1], fmaxf(x1, y1));
            }
        }

        // ---- per-tile flush: reduce over row-groups, atomicMax (disjoint cols) ----
#pragma unroll
        for (int nt = 0; nt < 2; nt++) {
#pragma unroll
            for (int j = 0; j < 2; j++) {
                float v = rm[nt][j];
                v = fmaxf(v, __shfl_xor_sync(0xFFFFFFFFu, v, 4));
                v = fmaxf(v, __shfl_xor_sync(0xFFFFFFFFu, v, 8));
                v = fmaxf(v, __shfl_xor_sync(0xFFFFFFFFu, v, 16));
                if (g == 0)
                    atomicMax(reinterpret_cast<int*>(&g_agg[bidx * F3 + nb3 + nt * 8 + 2 * c + j]),
                              __float_as_int(v));
            }
        }
        __syncthreads();    // h1/h2/s_wid safe for next pop
    }
}

__global__ void __launch_bounds__(256)
rho_kernel(const float* __restrict__ r1w, const float* __restrict__ r1b,
           const float* __restrict__ r2w, const float* __restrict__ r2b,
           const float* __restrict__ r3w, const float* __restrict__ r3b,
           float* __restrict__ out)
{
    __shared__ float a[256], z1[256], z2[128];
    const int b   = blockIdx.x;
    const int tid = threadIdx.x;

    a[tid] = g_agg[b * F3 + tid];
    __syncthreads();

    float acc = r1b[tid];
#pragma unroll 4
    for (int k = 0; k < 256; k++) acc = fmaf(a[k], r1w[k * 256 + tid], acc);
    z1[tid] = fmaxf(acc, 0.0f);
    __syncthreads();

    if (tid < 128) {
        float acc2 = r2b[tid];
#pragma unroll 4
        for (int k = 0; k < 256; k++) acc2 = fmaf(z1[k], r2w[k * 128 + tid], acc2);
        z2[tid] = fmaxf(acc2, 0.0f);
    }
    __syncthreads();

    if (tid < 64) {
        float acc3 = r3b[tid];
#pragma unroll 4
        for (int k = 0; k < 128; k++) acc3 = fmaf(z2[k], r3w[k * 64 + tid], acc3);
        out[b * OUT + tid] = acc3;
    }
}

// ---------------- launch ----------------
extern "C" void kernel_launch(void* const* d_in, const int* in_sizes, int n_in,
                              void* d_out, int out_size)
{
    (void)in_sizes; (void)n_in; (void)out_size;
    const float* points = (const float*)d_in[0];
    const int*   lengths= (const int*)  d_in[1];
    const float* w1  = (const float*)d_in[2];
    const float* b1  = (const float*)d_in[3];
    const float* w2  = (const float*)d_in[4];
    const float* b2  = (const float*)d_in[5];
    const float* w3  = (const float*)d_in[6];
    const float* b3  = (const float*)d_in[7];
    const float* r1w = (const float*)d_in[8];
    const float* r1b = (const float*)d_in[9];
    const float* r2w = (const float*)d_in[10];
    const float* r2b = (const float*)d_in[11];
    const float* r3w = (const float*)d_in[12];
    const float* r3b = (const float*)d_in[13];

    cudaFuncSetAttribute(phi_mma_kernel,
                         cudaFuncAttributeMaxDynamicSharedMemorySize, SMEM_TOTAL);

    prep_kernel<<<128, 256>>>(w2, w3);
    phi_mma_kernel<<<GRID, NT, SMEM_TOTAL>>>(points, lengths, w1, b1, b2, b3);
    rho_kernel<<<B, 256>>>(r1w, r1b, r2w, r2b, r3w, r3b, (float*)d_out);
}

// round 10
// speedup vs baseline: 1.9991x; 1.0755x over previous
#include <cuda_runtime.h>
#include <cuda_fp16.h>
#include <cstdint>

// ---------------- problem constants ----------------
constexpr int B   = 128;
constexpr int N   = 4096;
constexpr int OUT = 64;
constexpr int F1 = 64, F2 = 128, F3 = 256;

constexpr int TILE  = 256;          // points per work item
constexpr int MAXT  = N / TILE;     // 16 tiles max per batch
constexpr int MAXW  = B * MAXT;     // 2048 work items
constexpr int GRID  = 152;          // persistent CTAs
constexpr int NT    = 512;          // threads (16 warps)

// half strides with +8 pad -> conflict-free fragment access
constexpr int S1H = 72;             // h1 / wt2 rows (k-dim 64)
constexpr int S3H = 136;            // h2 / wt3 rows (k-dim 128)
constexpr int S1W = S1H / 2;        // 36 words
constexpr int S3W = S3H / 2;        // 68 words

__device__ float g_agg[B * F3];
__device__ int   g_work;
__device__ __align__(16) __half wt2g[F2 * S1H];   // [128 n][72 k] fp16
__device__ __align__(16) __half wt3g[F3 * S3H];   // [256 n][136 k] fp16

// ---------------- smem layout (bytes) ----------------
constexpr int OFF_W1  = 0;                          // 128 floats
constexpr int OFF_B1  = 512;                        // 64 floats
constexpr int OFF_POP = 768;                        // 2 ints (w, len)
constexpr int OFF_H1  = 1024;                       // 256*72 halves = 36864 B
constexpr int OFF_H2  = OFF_H1 + TILE * S1H * 2;    // 37888
constexpr int SMEM_TOTAL = OFF_H2 + TILE * S3H * 2; // 107520 B

__device__ __forceinline__ void mma_f16(float* d,
                                        uint32_t a0, uint32_t a1, uint32_t a2, uint32_t a3,
                                        uint32_t b0, uint32_t b1) {
    asm volatile(
        "mma.sync.aligned.m16n8k16.row.col.f32.f16.f16.f32 "
        "{%0,%1,%2,%3}, {%4,%5,%6,%7}, {%8,%9}, {%0,%1,%2,%3};"
        : "+f"(d[0]), "+f"(d[1]), "+f"(d[2]), "+f"(d[3])
        : "r"(a0), "r"(a1), "r"(a2), "r"(a3), "r"(b0), "r"(b1));
}

__device__ __forceinline__ void ldsm4(uint32_t& r0, uint32_t& r1, uint32_t& r2, uint32_t& r3,
                                      uint32_t saddr) {
    asm volatile("ldmatrix.sync.aligned.m8n8.x4.shared.b16 {%0,%1,%2,%3}, [%4];"
                 : "=r"(r0), "=r"(r1), "=r"(r2), "=r"(r3) : "r"(saddr));
}

__device__ __forceinline__ uint32_t packh2(float lo, float hi) {
    __half2 h = __floats2half2_rn(lo, hi);
    return *reinterpret_cast<uint32_t*>(&h);
}

__device__ __forceinline__ uint32_t smem_u32(const void* p) {
    uint32_t a;
    asm("{ .reg .u64 t; cvta.to.shared.u64 t, %1; cvt.u32.u64 %0, t; }" : "=r"(a) : "l"(p));
    return a;
}

// ---------------- prep: reset counter/agg + convert weights ----------------
__global__ void prep_kernel(const float* __restrict__ w2, const float* __restrict__ w3) {
    int i = blockIdx.x * 256 + threadIdx.x;
    if (i == 0) g_work = 0;
    if (i < B * F3) g_agg[i] = 0.0f;
    if (i < F1 * F2) {           // w2: [64 k][128 n] -> wt2g[n][k]
        int k = i >> 7, n = i & 127;
        wt2g[n * S1H + k] = __float2half_rn(w2[i]);
    }
    if (i < F2 * F3) {           // w3: [128 k][256 n] -> wt3g[n][k]
        int k = i >> 8, n = i & 255;
        wt3g[n * S3H + k] = __float2half_rn(w3[i]);
    }
}

// ---------------- phi: persistent, 2 barriers per 256-pt tile ----------------
__global__ void __launch_bounds__(NT, 1)
phi_mma_kernel(const float* __restrict__ points, const int* __restrict__ lengths,
               const float* __restrict__ w1, const float* __restrict__ b1,
               const float* __restrict__ b2, const float* __restrict__ b3)
{
    extern __shared__ char smem[];
    float* w1s  = reinterpret_cast<float*>(smem + OFF_W1);
    float* b1s  = reinterpret_cast<float*>(smem + OFF_B1);
    int*   spop = reinterpret_cast<int*>(smem + OFF_POP);
    uint32_t* h1w = reinterpret_cast<uint32_t*>(smem + OFF_H1);
    uint32_t* h2w = reinterpret_cast<uint32_t*>(smem + OFF_H2);
    const uint32_t sb = smem_u32(smem);

    const int tid  = threadIdx.x;
    const int lane = tid & 31;
    const int wid  = tid >> 5;         // 0..15
    const int g    = lane >> 2;        // row group 0..7
    const int c    = lane & 3;         // col-in-group 0..3
    const int nb2  = wid * 8;          // L2 n-slice (8 cols)
    const int nb3  = wid * 16;         // L3 n-slice (16 cols)

    if (tid < 128) w1s[tid] = w1[tid];
    else if (tid < 192) b1s[tid - 128] = b1[tid - 128];

    // ---- persistent B fragments + biases (registers) ----
    const uint32_t* w2w = reinterpret_cast<const uint32_t*>(wt2g);
    const uint32_t* w3w = reinterpret_cast<const uint32_t*>(wt3g);
    uint32_t b2r[4][2];
#pragma unroll
    for (int ks = 0; ks < 4; ks++) {
        const int base = (nb2 + g) * S1W + ks * 8 + c;
        b2r[ks][0] = w2w[base];
        b2r[ks][1] = w2w[base + 4];
    }
    uint32_t b3r[2][8][2];
#pragma unroll
    for (int nt = 0; nt < 2; nt++)
#pragma unroll
        for (int ks = 0; ks < 8; ks++) {
            const int base = (nb3 + nt * 8 + g) * S3W + ks * 8 + c;
            b3r[nt][ks][0] = w3w[base];
            b3r[nt][ks][1] = w3w[base + 4];
        }
    float bb2[2], bb3[2][2];
    bb2[0] = b2[nb2 + 2 * c];
    bb2[1] = b2[nb2 + 2 * c + 1];
#pragma unroll
    for (int nt = 0; nt < 2; nt++) {
        bb3[nt][0] = b3[nb3 + nt * 8 + 2 * c];
        bb3[nt][1] = b3[nb3 + nt * 8 + 2 * c + 1];
    }

    // ---- ldmatrix per-lane base addresses ----
    const int tsel = lane >> 3, rr = lane & 7;
    const int lrow = (tsel & 1) * 8 + rr;
    const int lcol = (tsel >> 1) * 4;          // word offset
    const uint32_t a1base = sb + OFF_H1 + (lrow * S1W + lcol) * 4;
    const uint32_t a2base = sb + OFF_H2 + (lrow * S3W + lcol) * 4;

    // ---- tid0 pop: skip invalid items without CTA barriers ----
    auto pop = [&]() {
        int ww = atomicAdd(&g_work, 1);
        int ll = 0;
        while (ww < MAXW) {
            const int bb = ww & (B - 1);
            ll = lengths[bb];
            if ((ww >> 7) * TILE < ll) break;
            ww = atomicAdd(&g_work, 1);
        }
        spop[0] = ww; spop[1] = ll;
    };

    if (tid == 0) pop();
    __syncthreads();
    int w = spop[0], len = spop[1];

    while (w < MAXW) {
        const int bidx   = w & (B - 1);
        const int base_m = (w >> 7) * TILE;
        const int rows   = min(TILE, len - base_m);
        const int mfmax  = (rows + 15) >> 4;

        // ---- A: layer 1 (2 -> 64), 256 points in two halves ----
        {
            const int p0 = tid >> 2, cl = tid & 3;
#pragma unroll
            for (int hh = 0; hh < 2; hh++) {
                const int p = p0 + hh * 128;
                if (p < rows) {
                    float2 pp = reinterpret_cast<const float2*>(points)[(long long)bidx * N + base_m + p];
                    const float x = pp.x, y = pp.y;
#pragma unroll
                    for (int i = 0; i < 8; i++) {
                        const int f = 8 * i + 2 * cl;
                        float v0 = fmaxf(fmaf(x, w1s[f],     fmaf(y, w1s[64 + f],     b1s[f])),     0.0f);
                        float v1 = fmaxf(fmaf(x, w1s[f + 1], fmaf(y, w1s[64 + f + 1], b1s[f + 1])), 0.0f);
                        h1w[p * S1W + 4 * i + cl] = packh2(v0, v1);
                    }
                }
            }
        }
        __syncthreads();    // sync1: h1 ready

        // ---- B: layer 2 (clipped to mfmax) + prefetch next work item ----
        for (int mf = 0; mf < mfmax; mf++) {
            float acc[4] = {0.0f, 0.0f, 0.0f, 0.0f};
#pragma unroll
            for (int ks = 0; ks < 4; ks++) {
                uint32_t a0, a1, a2, a3;
                ldsm4(a0, a1, a2, a3, a1base + (mf * 16 * S1W + ks * 8) * 4);
                mma_f16(acc, a0, a1, a2, a3, b2r[ks][0], b2r[ks][1]);
            }
            const int r0 = mf * 16 + g, r1 = r0 + 8;
            const int cw = nb2 / 2 + c;
            h2w[r0 * S3W + cw] = packh2(fmaxf(acc[0] + bb2[0], 0.0f),
                                        fmaxf(acc[1] + bb2[1], 0.0f));
            h2w[r1 * S3W + cw] = packh2(fmaxf(acc[2] + bb2[0], 0.0f),
                                        fmaxf(acc[3] + bb2[1], 0.0f));
        }
        if (tid == 0) pop();
        __syncthreads();    // sync2: h2 ready + next item ready
        const int wn = spop[0], lenn = spop[1];

        // ---- C: layer 3 (clipped) + per-tile max flush ----
        float rm[2][2] = {{0.0f, 0.0f}, {0.0f, 0.0f}};
        for (int mf = 0; mf < mfmax; mf++) {
            float acc[2][4];
#pragma unroll
            for (int nt = 0; nt < 2; nt++)
#pragma unroll
                for (int j = 0; j < 4; j++) acc[nt][j] = 0.0f;

#pragma unroll
            for (int ks = 0; ks < 8; ks++) {
                uint32_t a0, a1, a2, a3;
                ldsm4(a0, a1, a2, a3, a2base + (mf * 16 * S3W + ks * 8) * 4);
#pragma unroll
                for (int nt = 0; nt < 2; nt++)
                    mma_f16(acc[nt], a0, a1, a2, a3, b3r[nt][ks][0], b3r[nt][ks][1]);
            }
            const int r0 = base_m + mf * 16 + g;
            const int r1 = r0 + 8;
            const bool v0 = r0 < len, v1 = r1 < len;
#pragma unroll
            for (int nt = 0; nt < 2; nt++) {
                float x0 = v0 ? fmaxf(acc[nt][0] + bb3[nt][0], 0.0f) : 0.0f;
                float x1 = v0 ? fmaxf(acc[nt][1] + bb3[nt][1], 0.0f) : 0.0f;
                float y0 = v1 ? fmaxf(acc[nt][2] + bb3[nt][0], 0.0f) : 0.0f;
                float y1 = v1 ? fmaxf(acc[nt][3] + bb3[nt][1], 0.0f) : 0.0f;
                rm[nt][0] = fmaxf(rm[nt][0], fmaxf(x0, y0));
                rm[nt][1] = fmaxf(rm[nt][1], fmaxf(x1, y1));
            }
        }
#pragma unroll
        for (int nt = 0; nt < 2; nt++) {
#pragma unroll
            for (int j = 0; j < 2; j++) {
                float v = rm[nt][j];
                v = fmaxf(v, __shfl_xor_sync(0xFFFFFFFFu, v, 4));
                v = fmaxf(v, __shfl_xor_sync(0xFFFFFFFFu, v, 8));
                v = fmaxf(v, __shfl_xor_sync(0xFFFFFFFFu, v, 16));
                if (g == 0)
                    atomicMax(reinterpret_cast<int*>(&g_agg[bidx * F3 + nb3 + nt * 8 + 2 * c + j]),
                              __float_as_int(v));
            }
        }
        w = wn; len = lenn;   // no end barrier: next L1 writes h1 only (C reads h2 only)
    }
}

__global__ void __launch_bounds__(256)
rho_kernel(const float* __restrict__ r1w, const float* __restrict__ r1b,
           const float* __restrict__ r2w, const float* __restrict__ r2b,
           const float* __restrict__ r3w, const float* __restrict__ r3b,
           float* __restrict__ out)
{
    __shared__ float a[256], z1[256], z2[128];
    const int b   = blockIdx.x;
    const int tid = threadIdx.x;

    a[tid] = g_agg[b * F3 + tid];
    __syncthreads();

    float acc = r1b[tid];
#pragma unroll 4
    for (int k = 0; k < 256; k++) acc = fmaf(a[k], r1w[k * 256 + tid], acc);
    z1[tid] = fmaxf(acc, 0.0f);
    __syncthreads();

    if (tid < 128) {
        float acc2 = r2b[tid];
#pragma unroll 4
        for (int k = 0; k < 256; k++) acc2 = fmaf(z1[k], r2w[k * 128 + tid], acc2);
        z2[tid] = fmaxf(acc2, 0.0f);
    }
    __syncthreads();

    if (tid < 64) {
        float acc3 = r3b[tid];
#pragma unroll 4
        for (int k = 0; k < 128; k++) acc3 = fmaf(z2[k], r3w[k * 64 + tid], acc3);
        out[b * OUT + tid] = acc3;
    }
}

// ---------------- launch ----------------
extern "C" void kernel_launch(void* const* d_in, const int* in_sizes, int n_in,
                              void* d_out, int out_size)
{
    (void)in_sizes; (void)n_in; (void)out_size;
    const float* points = (const float*)d_in[0];
    const int*   lengths= (const int*)  d_in[1];
    const float* w1  = (const float*)d_in[2];
    const float* b1  = (const float*)d_in[3];
    const float* w2  = (const float*)d_in[4];
    const float* b2  = (const float*)d_in[5];
    const float* w3  = (const float*)d_in[6];
    const float* b3  = (const float*)d_in[7];
    const float* r1w = (const float*)d_in[8];
    const float* r1b = (const float*)d_in[9];
    const float* r2w = (const float*)d_in[10];
    const float* r2b = (const float*)d_in[11];
    const float* r3w = (const float*)d_in[12];
    const float* r3b = (const float*)d_in[13];

    cudaFuncSetAttribute(phi_mma_kernel,
                         cudaFuncAttributeMaxDynamicSharedMemorySize, SMEM_TOTAL);

    prep_kernel<<<128, 256>>>(w2, w3);
    phi_mma_kernel<<<GRID, NT, SMEM_TOTAL>>>(points, lengths, w1, b1, b2, b3);
    rho_kernel<<<B, 256>>>(r1w, r1b, r2w, r2b, r3w, r3b, (float*)d_out);
}